// round 2
// baseline (speedup 1.0000x reference)
#include <cuda_runtime.h>
#include <cstdint>

// Problem constants
constexpr int Ktok = 77;
constexpr int Dd   = 768;
constexpr int Nv   = 576;
constexpr int RS   = 256 * 768;         // row stride (k or n) in floats: B*D
constexpr int TEXT_ELEMS   = 77 * 256 * 768;
constexpr int VISION_ELEMS = 576 * 256 * 768;

// SMEM layout (floats)
constexpr int S_STR  = 580;             // S row stride (580 mod 32 == 4 -> conflict-free frags)
constexpr int S_OFF  = 0;
constexpr int STG    = 77 * S_STR + 12; // 44660 -> 44672 (16B aligned)
constexpr int ST1    = 20;              // phase-1 tile stride (d-chunk 16 + pad 4)
constexpr int T_HI   = STG;             // 96 x 20
constexpr int T_LO   = T_HI + 96 * ST1;
constexpr int V_HI   = T_LO + 96 * ST1;
constexpr int V_LO   = V_HI + 96 * ST1;
constexpr int SMEM_FLOATS = V_LO + 96 * ST1;      // 52352
constexpr int SMEM_BYTES  = SMEM_FLOATS * 4;      // 209408 B  (< 227 KB cap)
constexpr int ST2    = 136;             // phase-2 V tile stride (128 + pad 8)
constexpr int V2     = STG;             // phase-2 V tile reuses staging region (32x136 fits)

__device__ __forceinline__ float to_tf32(float x) {
    uint32_t u;
    asm("cvt.rna.tf32.f32 %0, %1;" : "=r"(u) : "f"(x));
    return __uint_as_float(u);
}

__device__ __forceinline__ float ex2(float x) {
    float y;
    asm("ex2.approx.f32 %0, %1;" : "=f"(y) : "f"(x));
    return y;
}

__device__ __forceinline__ void mma8(float* c,
                                     float a0, float a1, float a2, float a3,
                                     float b0, float b1) {
    asm volatile(
        "mma.sync.aligned.m16n8k8.row.col.f32.tf32.tf32.f32 "
        "{%0,%1,%2,%3}, {%4,%5,%6,%7}, {%8,%9}, {%0,%1,%2,%3};\n"
        : "+f"(c[0]), "+f"(c[1]), "+f"(c[2]), "+f"(c[3])
        : "r"(__float_as_uint(a0)), "r"(__float_as_uint(a1)),
          "r"(__float_as_uint(a2)), "r"(__float_as_uint(a3)),
          "r"(__float_as_uint(b0)), "r"(__float_as_uint(b1)));
}

extern __shared__ float sm[];

__global__ __launch_bounds__(256, 1)
void ShallowDecoder_kernel(const float* __restrict__ text,
                           const float* __restrict__ vision,
                           float* __restrict__ out) {
    const int b = blockIdx.x;
    const float* tb = text + b * Dd;
    const float* vb = vision + b * Dd;
    float* ob = out + b * Dd;

    const int tid  = threadIdx.x;
    const int w    = tid >> 5;
    const int lane = tid & 31;
    const int wm   = w >> 2;      // 0..1 : covers 48 M-rows
    const int wn   = w & 3;       // 0..3
    const int g    = lane >> 2;   // groupID
    const int c    = lane & 3;    // threadID_in_group

    // ================= Phase 1: S = T V^T  (3xTF32) =================
    for (int nt = 0; nt < 6; ++nt) {
        const int nb = nt * 96;

        float acc[3][3][4];
        #pragma unroll
        for (int mt = 0; mt < 3; ++mt)
            #pragma unroll
            for (int nc = 0; nc < 3; ++nc)
                #pragma unroll
                for (int q = 0; q < 4; ++q) acc[mt][nc][q] = 0.f;

        float2 pT[3], pV[3];
        // prefetch chunk 0
        #pragma unroll
        for (int q = 0; q < 3; ++q) {
            int i = tid + 256 * q;
            int m = i >> 3, j = i & 7;
            int mr = m > 76 ? 76 : m;
            pT[q] = *(const float2*)(tb + (size_t)mr * RS + 2 * j);
            pV[q] = *(const float2*)(vb + (size_t)(nb + m) * RS + 2 * j);
        }

        for (int dc = 0; dc < 48; ++dc) {
            // stage prefetched regs -> smem (hi/lo tf32 split)
            #pragma unroll
            for (int q = 0; q < 3; ++q) {
                int i = tid + 256 * q;
                int m = i >> 3, j = i & 7;
                float2 h, l;
                h.x = to_tf32(pT[q].x); h.y = to_tf32(pT[q].y);
                l.x = pT[q].x - h.x;    l.y = pT[q].y - h.y;
                *(float2*)&sm[T_HI + m * ST1 + 2 * j] = h;
                *(float2*)&sm[T_LO + m * ST1 + 2 * j] = l;
                h.x = to_tf32(pV[q].x); h.y = to_tf32(pV[q].y);
                l.x = pV[q].x - h.x;    l.y = pV[q].y - h.y;
                *(float2*)&sm[V_HI + m * ST1 + 2 * j] = h;
                *(float2*)&sm[V_LO + m * ST1 + 2 * j] = l;
            }
            __syncthreads();

            // prefetch next chunk while mma runs
            if (dc < 47) {
                const int d0 = (dc + 1) * 16;
                #pragma unroll
                for (int q = 0; q < 3; ++q) {
                    int i = tid + 256 * q;
                    int m = i >> 3, j = i & 7;
                    int mr = m > 76 ? 76 : m;
                    pT[q] = *(const float2*)(tb + (size_t)mr * RS + d0 + 2 * j);
                    pV[q] = *(const float2*)(vb + (size_t)(nb + m) * RS + d0 + 2 * j);
                }
            }

            #pragma unroll
            for (int kk = 0; kk < 2; ++kk) {
                float bh[3][2], bl[3][2];
                #pragma unroll
                for (int nc = 0; nc < 3; ++nc) {
                    int bn = wn * 24 + nc * 8 + g;
                    int ba = bn * ST1 + kk * 8 + c;
                    bh[nc][0] = sm[V_HI + ba];     bh[nc][1] = sm[V_HI + ba + 4];
                    bl[nc][0] = sm[V_LO + ba];     bl[nc][1] = sm[V_LO + ba + 4];
                }
                #pragma unroll
                for (int mt = 0; mt < 3; ++mt) {
                    int mr = wm * 48 + mt * 16 + g;
                    int aa = mr * ST1 + kk * 8 + c;
                    float ah0 = sm[T_HI + aa];
                    float ah1 = sm[T_HI + aa + 8 * ST1];
                    float ah2 = sm[T_HI + aa + 4];
                    float ah3 = sm[T_HI + aa + 8 * ST1 + 4];
                    float al0 = sm[T_LO + aa];
                    float al1 = sm[T_LO + aa + 8 * ST1];
                    float al2 = sm[T_LO + aa + 4];
                    float al3 = sm[T_LO + aa + 8 * ST1 + 4];
                    #pragma unroll
                    for (int nc = 0; nc < 3; ++nc) {
                        mma8(acc[mt][nc], ah0, ah1, ah2, ah3, bh[nc][0], bh[nc][1]);
                        mma8(acc[mt][nc], ah0, ah1, ah2, ah3, bl[nc][0], bl[nc][1]);
                        mma8(acc[mt][nc], al0, al1, al2, al3, bh[nc][0], bh[nc][1]);
                    }
                }
            }
            __syncthreads();
        }

        // store S tile (guard rows < 77)
        #pragma unroll
        for (int mt = 0; mt < 3; ++mt) {
            int r0 = wm * 48 + mt * 16 + g, r1 = r0 + 8;
            #pragma unroll
            for (int nc = 0; nc < 3; ++nc) {
                int col = nb + wn * 24 + nc * 8 + 2 * c;
                if (r0 < 77)
                    *(float2*)&sm[S_OFF + r0 * S_STR + col] =
                        make_float2(acc[mt][nc][0], acc[mt][nc][1]);
                if (r1 < 77)
                    *(float2*)&sm[S_OFF + r1 * S_STR + col] =
                        make_float2(acc[mt][nc][2], acc[mt][nc][3]);
            }
        }
    }
    __syncthreads();

    // ================= Softmax over n (axis 576), temp 0.07 =================
    {
        const float SCL = 20.60992915555662f; // log2(e)/0.07
        for (int r = w; r < 77; r += 8) {
            float v[18];
            float mx = -1e30f;
            #pragma unroll
            for (int j = 0; j < 18; ++j) {
                v[j] = sm[r * S_STR + lane + 32 * j];
                mx = fmaxf(mx, v[j]);
            }
            #pragma unroll
            for (int o = 16; o > 0; o >>= 1)
                mx = fmaxf(mx, __shfl_xor_sync(0xffffffffu, mx, o));
            float sum = 0.f;
            #pragma unroll
            for (int j = 0; j < 18; ++j) {
                v[j] = ex2((v[j] - mx) * SCL);
                sum += v[j];
            }
            #pragma unroll
            for (int o = 16; o > 0; o >>= 1)
                sum += __shfl_xor_sync(0xffffffffu, sum, o);
            float rinv = 1.0f / sum;
            #pragma unroll
            for (int j = 0; j < 18; ++j)
                sm[r * S_STR + lane + 32 * j] = v[j] * rinv;
        }
    }
    __syncthreads();

    // ================= Phase 2: O = A V  (2xTF32, split A) =================
    int arow[3][2];
    #pragma unroll
    for (int mt = 0; mt < 3; ++mt) {
        int r0 = wm * 48 + mt * 16 + g;
        int r1 = r0 + 8;
        arow[mt][0] = (r0 > 76 ? 76 : r0) * S_STR;
        arow[mt][1] = (r1 > 76 ? 76 : r1) * S_STR;
    }

    for (int dt = 0; dt < 6; ++dt) {
        const int db = dt * 128;

        float acc[3][4][4];
        #pragma unroll
        for (int mt = 0; mt < 3; ++mt)
            #pragma unroll
            for (int d8 = 0; d8 < 4; ++d8)
                #pragma unroll
                for (int q = 0; q < 4; ++q) acc[mt][d8][q] = 0.f;

        float2 pv[8];
        #pragma unroll
        for (int q = 0; q < 8; ++q) {
            int i = tid + 256 * q;
            int n = i >> 6, j = i & 63;
            pv[q] = *(const float2*)(vb + (size_t)n * RS + db + 2 * j);
        }

        for (int ch = 0; ch < 18; ++ch) {
            #pragma unroll
            for (int q = 0; q < 8; ++q) {
                int i = tid + 256 * q;
                int n = i >> 6, j = i & 63;
                float2 h;
                h.x = to_tf32(pv[q].x);
                h.y = to_tf32(pv[q].y);
                *(float2*)&sm[V2 + n * ST2 + 2 * j] = h;
            }
            __syncthreads();

            if (ch < 17) {
                #pragma unroll
                for (int q = 0; q < 8; ++q) {
                    int i = tid + 256 * q;
                    int n = i >> 6, j = i & 63;
                    pv[q] = *(const float2*)(vb + (size_t)((ch + 1) * 32 + n) * RS + db + 2 * j);
                }
            }

            const int nbase = ch * 32;
            #pragma unroll
            for (int kk = 0; kk < 4; ++kk) {
                float bv[4][2];
                #pragma unroll
                for (int d8 = 0; d8 < 4; ++d8) {
                    int col = wn * 32 + d8 * 8 + g;
                    bv[d8][0] = sm[V2 + (kk * 8 + c) * ST2 + col];
                    bv[d8][1] = sm[V2 + (kk * 8 + c + 4) * ST2 + col];
                }
                #pragma unroll
                for (int mt = 0; mt < 3; ++mt) {
                    int ca = nbase + kk * 8 + c;
                    float a0 = sm[arow[mt][0] + ca];
                    float a1 = sm[arow[mt][1] + ca];
                    float a2 = sm[arow[mt][0] + ca + 4];
                    float a3 = sm[arow[mt][1] + ca + 4];
                    float h0 = to_tf32(a0), h1 = to_tf32(a1),
                          h2 = to_tf32(a2), h3 = to_tf32(a3);
                    float l0 = a0 - h0, l1 = a1 - h1, l2 = a2 - h2, l3 = a3 - h3;
                    #pragma unroll
                    for (int d8 = 0; d8 < 4; ++d8) {
                        mma8(acc[mt][d8], h0, h1, h2, h3, bv[d8][0], bv[d8][1]);
                        mma8(acc[mt][d8], l0, l1, l2, l3, bv[d8][0], bv[d8][1]);
                    }
                }
            }
            __syncthreads();
        }

        // store output tile (fp32, guard rows < 77)
        #pragma unroll
        for (int mt = 0; mt < 3; ++mt) {
            int r0 = wm * 48 + mt * 16 + g, r1 = r0 + 8;
            #pragma unroll
            for (int d8 = 0; d8 < 4; ++d8) {
                int col = db + wn * 32 + d8 * 8 + 2 * c;
                if (r0 < 77)
                    *(float2*)(ob + (size_t)r0 * RS + col) =
                        make_float2(acc[mt][d8][0], acc[mt][d8][1]);
                if (r1 < 77)
                    *(float2*)(ob + (size_t)r1 * RS + col) =
                        make_float2(acc[mt][d8][2], acc[mt][d8][3]);
            }
        }
    }
}

extern "C" void kernel_launch(void* const* d_in, const int* in_sizes, int n_in,
                              void* d_out, int out_size) {
    const float* text   = (const float*)d_in[0];
    const float* vision = (const float*)d_in[1];
    // defensive: identify operands by element count
    if (n_in >= 2 && in_sizes[0] == VISION_ELEMS && in_sizes[1] == TEXT_ELEMS) {
        const float* t = text;
        text = vision;
        vision = t;
    }
    cudaFuncSetAttribute(ShallowDecoder_kernel,
                         cudaFuncAttributeMaxDynamicSharedMemorySize, SMEM_BYTES);
    ShallowDecoder_kernel<<<256, 256, SMEM_BYTES>>>(text, vision, (float*)d_out);
}

// round 3
// speedup vs baseline: 1.0523x; 1.0523x over previous
#include <cuda_runtime.h>
#include <cstdint>

// Problem constants
constexpr int Dd   = 768;
constexpr int RS   = 256 * 768;         // row stride (k or n) in floats: B*D
constexpr int TEXT_ELEMS   = 77 * 256 * 768;
constexpr int VISION_ELEMS = 576 * 256 * 768;

// SMEM layout (floats)
constexpr int S_STR  = 580;             // S row stride (580 mod 32 == 4 -> conflict-free frags)
constexpr int S_OFF  = 0;
constexpr int STG    = 77 * S_STR + 12; // 44660 -> 44672 (16B aligned)
constexpr int ST1    = 20;              // phase-1 tile stride (d-chunk 16 + pad 4)
constexpr int T_HI   = STG;             // 96 x 20
constexpr int T_LO   = T_HI + 96 * ST1;
constexpr int V_HI   = T_LO + 96 * ST1;
constexpr int V_LO   = V_HI + 192 * ST1;
constexpr int SMEM_FLOATS = V_LO + 192 * ST1;     // 56192 floats
constexpr int SMEM_BYTES  = SMEM_FLOATS * 4;      // 224768 B (< 227 KB cap)
constexpr int ST2    = 200;             // phase-2 V tile stride (192 + pad 8)
constexpr int V2     = STG;             // phase-2 V tile reuses staging region (32x200 fits)

__device__ __forceinline__ float to_tf32(float x) {
    uint32_t u;
    asm("cvt.rna.tf32.f32 %0, %1;" : "=r"(u) : "f"(x));
    return __uint_as_float(u);
}

__device__ __forceinline__ float ex2(float x) {
    float y;
    asm("ex2.approx.f32 %0, %1;" : "=f"(y) : "f"(x));
    return y;
}

__device__ __forceinline__ void mma8(float* c,
                                     float a0, float a1, float a2, float a3,
                                     float b0, float b1) {
    asm volatile(
        "mma.sync.aligned.m16n8k8.row.col.f32.tf32.tf32.f32 "
        "{%0,%1,%2,%3}, {%4,%5,%6,%7}, {%8,%9}, {%0,%1,%2,%3};\n"
        : "+f"(c[0]), "+f"(c[1]), "+f"(c[2]), "+f"(c[3])
        : "r"(__float_as_uint(a0)), "r"(__float_as_uint(a1)),
          "r"(__float_as_uint(a2)), "r"(__float_as_uint(a3)),
          "r"(__float_as_uint(b0)), "r"(__float_as_uint(b1)));
}

extern __shared__ float sm[];

__global__ __launch_bounds__(512, 1)
void ShallowDecoder_kernel(const float* __restrict__ text,
                           const float* __restrict__ vision,
                           float* __restrict__ out) {
    const int b = blockIdx.x;
    const float* tb = text + b * Dd;
    const float* vb = vision + b * Dd;
    float* ob = out + b * Dd;

    const int tid  = threadIdx.x;
    const int w    = tid >> 5;
    const int lane = tid & 31;
    const int wm   = w >> 3;      // 0..1 : 48 M-rows each
    const int wn   = w & 7;       // 0..7
    const int g    = lane >> 2;   // groupID
    const int c    = lane & 3;    // threadID_in_group

    // ================= Phase 1: S = T V^T  (3xTF32), N-tile 192 =================
    for (int nt = 0; nt < 3; ++nt) {
        const int nb = nt * 192;

        float acc[3][3][4];
        #pragma unroll
        for (int mt = 0; mt < 3; ++mt)
            #pragma unroll
            for (int nc = 0; nc < 3; ++nc)
                #pragma unroll
                for (int q = 0; q < 4; ++q) acc[mt][nc][q] = 0.f;

        float2 pT[2], pV[3];
        // prefetch chunk 0
        #pragma unroll
        for (int q = 0; q < 2; ++q) {
            int i = tid + 512 * q;
            if (i < 768) {
                int m = i >> 3, j = i & 7;
                int mr = m > 76 ? 76 : m;
                pT[q] = *(const float2*)(tb + (size_t)mr * RS + 2 * j);
            }
        }
        #pragma unroll
        for (int q = 0; q < 3; ++q) {
            int i = tid + 512 * q;        // 0..1535
            int m = i >> 3, j = i & 7;    // m 0..191
            pV[q] = *(const float2*)(vb + (size_t)(nb + m) * RS + 2 * j);
        }

        for (int dc = 0; dc < 48; ++dc) {
            // stage prefetched regs -> smem (hi/lo tf32 split)
            #pragma unroll
            for (int q = 0; q < 2; ++q) {
                int i = tid + 512 * q;
                if (i < 768) {
                    int m = i >> 3, j = i & 7;
                    float2 h, l;
                    h.x = to_tf32(pT[q].x); h.y = to_tf32(pT[q].y);
                    l.x = pT[q].x - h.x;    l.y = pT[q].y - h.y;
                    *(float2*)&sm[T_HI + m * ST1 + 2 * j] = h;
                    *(float2*)&sm[T_LO + m * ST1 + 2 * j] = l;
                }
            }
            #pragma unroll
            for (int q = 0; q < 3; ++q) {
                int i = tid + 512 * q;
                int m = i >> 3, j = i & 7;
                float2 h, l;
                h.x = to_tf32(pV[q].x); h.y = to_tf32(pV[q].y);
                l.x = pV[q].x - h.x;    l.y = pV[q].y - h.y;
                *(float2*)&sm[V_HI + m * ST1 + 2 * j] = h;
                *(float2*)&sm[V_LO + m * ST1 + 2 * j] = l;
            }
            __syncthreads();

            // prefetch next chunk while mma runs
            if (dc < 47) {
                const int d0 = (dc + 1) * 16;
                #pragma unroll
                for (int q = 0; q < 2; ++q) {
                    int i = tid + 512 * q;
                    if (i < 768) {
                        int m = i >> 3, j = i & 7;
                        int mr = m > 76 ? 76 : m;
                        pT[q] = *(const float2*)(tb + (size_t)mr * RS + d0 + 2 * j);
                    }
                }
                #pragma unroll
                for (int q = 0; q < 3; ++q) {
                    int i = tid + 512 * q;
                    int m = i >> 3, j = i & 7;
                    pV[q] = *(const float2*)(vb + (size_t)(nb + m) * RS + d0 + 2 * j);
                }
            }

            #pragma unroll
            for (int kk = 0; kk < 2; ++kk) {
                float bh[3][2], bl[3][2];
                #pragma unroll
                for (int nc = 0; nc < 3; ++nc) {
                    int bn = wn * 24 + nc * 8 + g;
                    int ba = bn * ST1 + kk * 8 + c;
                    bh[nc][0] = sm[V_HI + ba];     bh[nc][1] = sm[V_HI + ba + 4];
                    bl[nc][0] = sm[V_LO + ba];     bl[nc][1] = sm[V_LO + ba + 4];
                }
                #pragma unroll
                for (int mt = 0; mt < 3; ++mt) {
                    int mr = wm * 48 + mt * 16 + g;
                    int aa = mr * ST1 + kk * 8 + c;
                    float ah0 = sm[T_HI + aa];
                    float ah1 = sm[T_HI + aa + 8 * ST1];
                    float ah2 = sm[T_HI + aa + 4];
                    float ah3 = sm[T_HI + aa + 8 * ST1 + 4];
                    float al0 = sm[T_LO + aa];
                    float al1 = sm[T_LO + aa + 8 * ST1];
                    float al2 = sm[T_LO + aa + 4];
                    float al3 = sm[T_LO + aa + 8 * ST1 + 4];
                    #pragma unroll
                    for (int nc = 0; nc < 3; ++nc) {
                        mma8(acc[mt][nc], ah0, ah1, ah2, ah3, bh[nc][0], bh[nc][1]);
                        mma8(acc[mt][nc], ah0, ah1, ah2, ah3, bl[nc][0], bl[nc][1]);
                        mma8(acc[mt][nc], al0, al1, al2, al3, bh[nc][0], bh[nc][1]);
                    }
                }
            }
            __syncthreads();
        }

        // store S tile (guard rows < 77)
        #pragma unroll
        for (int mt = 0; mt < 3; ++mt) {
            int r0 = wm * 48 + mt * 16 + g, r1 = r0 + 8;
            #pragma unroll
            for (int nc = 0; nc < 3; ++nc) {
                int col = nb + wn * 24 + nc * 8 + 2 * c;
                if (r0 < 77)
                    *(float2*)&sm[S_OFF + r0 * S_STR + col] =
                        make_float2(acc[mt][nc][0], acc[mt][nc][1]);
                if (r1 < 77)
                    *(float2*)&sm[S_OFF + r1 * S_STR + col] =
                        make_float2(acc[mt][nc][2], acc[mt][nc][3]);
            }
        }
    }
    __syncthreads();

    // ================= Softmax over n (axis 576), temp 0.07 =================
    {
        const float SCL = 20.60992915555662f; // log2(e)/0.07
        for (int r = w; r < 77; r += 16) {
            float v[18];
            float mx = -1e30f;
            #pragma unroll
            for (int j = 0; j < 18; ++j) {
                v[j] = sm[r * S_STR + lane + 32 * j];
                mx = fmaxf(mx, v[j]);
            }
            #pragma unroll
            for (int o = 16; o > 0; o >>= 1)
                mx = fmaxf(mx, __shfl_xor_sync(0xffffffffu, mx, o));
            float sum = 0.f;
            #pragma unroll
            for (int j = 0; j < 18; ++j) {
                v[j] = ex2((v[j] - mx) * SCL);
                sum += v[j];
            }
            #pragma unroll
            for (int o = 16; o > 0; o >>= 1)
                sum += __shfl_xor_sync(0xffffffffu, sum, o);
            float rinv = 1.0f / sum;
            #pragma unroll
            for (int j = 0; j < 18; ++j)
                sm[r * S_STR + lane + 32 * j] = v[j] * rinv;
        }
    }
    __syncthreads();

    // ================= Phase 2: O = A V  (2xTF32, split A), d-tile 192 =================
    int arow[3][2];
    #pragma unroll
    for (int mt = 0; mt < 3; ++mt) {
        int r0 = wm * 48 + mt * 16 + g;
        int r1 = r0 + 8;
        arow[mt][0] = (r0 > 76 ? 76 : r0) * S_STR;
        arow[mt][1] = (r1 > 76 ? 76 : r1) * S_STR;
    }

    const int trow = tid >> 4;        // 0..31  (V2 tile row)
    const int tcol = tid & 15;        // 16 threads per row

    for (int dt = 0; dt < 4; ++dt) {
        const int db = dt * 192;

        float acc[3][3][4];
        #pragma unroll
        for (int mt = 0; mt < 3; ++mt)
            #pragma unroll
            for (int d8 = 0; d8 < 3; ++d8)
                #pragma unroll
                for (int q = 0; q < 4; ++q) acc[mt][d8][q] = 0.f;

        float2 pv[6];
        #pragma unroll
        for (int q = 0; q < 6; ++q) {
            int j = tcol + 16 * q;       // 0..95 float2 within row
            pv[q] = *(const float2*)(vb + (size_t)trow * RS + db + 2 * j);
        }

        for (int ch = 0; ch < 18; ++ch) {
            #pragma unroll
            for (int q = 0; q < 6; ++q) {
                int j = tcol + 16 * q;
                float2 h;
                h.x = to_tf32(pv[q].x);
                h.y = to_tf32(pv[q].y);
                *(float2*)&sm[V2 + trow * ST2 + 2 * j] = h;
            }
            __syncthreads();

            if (ch < 17) {
                #pragma unroll
                for (int q = 0; q < 6; ++q) {
                    int j = tcol + 16 * q;
                    pv[q] = *(const float2*)(vb + (size_t)((ch + 1) * 32 + trow) * RS + db + 2 * j);
                }
            }

            const int nbase = ch * 32;
            #pragma unroll
            for (int kk = 0; kk < 4; ++kk) {
                float bv[3][2];
                #pragma unroll
                for (int d8 = 0; d8 < 3; ++d8) {
                    int col = wn * 24 + d8 * 8 + g;
                    bv[d8][0] = sm[V2 + (kk * 8 + c) * ST2 + col];
                    bv[d8][1] = sm[V2 + (kk * 8 + c + 4) * ST2 + col];
                }
                #pragma unroll
                for (int mt = 0; mt < 3; ++mt) {
                    int ca = nbase + kk * 8 + c;
                    float a0 = sm[arow[mt][0] + ca];
                    float a1 = sm[arow[mt][1] + ca];
                    float a2 = sm[arow[mt][0] + ca + 4];
                    float a3 = sm[arow[mt][1] + ca + 4];
                    float h0 = to_tf32(a0), h1 = to_tf32(a1),
                          h2 = to_tf32(a2), h3 = to_tf32(a3);
                    float l0 = a0 - h0, l1 = a1 - h1, l2 = a2 - h2, l3 = a3 - h3;
                    #pragma unroll
                    for (int d8 = 0; d8 < 3; ++d8) {
                        mma8(acc[mt][d8], h0, h1, h2, h3, bv[d8][0], bv[d8][1]);
                        mma8(acc[mt][d8], l0, l1, l2, l3, bv[d8][0], bv[d8][1]);
                    }
                }
            }
            __syncthreads();
        }

        // store output tile (fp32, guard rows < 77)
        #pragma unroll
        for (int mt = 0; mt < 3; ++mt) {
            int r0 = wm * 48 + mt * 16 + g, r1 = r0 + 8;
            #pragma unroll
            for (int d8 = 0; d8 < 3; ++d8) {
                int col = db + wn * 24 + d8 * 8 + 2 * c;
                if (r0 < 77)
                    *(float2*)(ob + (size_t)r0 * RS + col) =
                        make_float2(acc[mt][d8][0], acc[mt][d8][1]);
                if (r1 < 77)
                    *(float2*)(ob + (size_t)r1 * RS + col) =
                        make_float2(acc[mt][d8][2], acc[mt][d8][3]);
            }
        }
    }
}

extern "C" void kernel_launch(void* const* d_in, const int* in_sizes, int n_in,
                              void* d_out, int out_size) {
    const float* text   = (const float*)d_in[0];
    const float* vision = (const float*)d_in[1];
    // defensive: identify operands by element count
    if (n_in >= 2 && in_sizes[0] == VISION_ELEMS && in_sizes[1] == TEXT_ELEMS) {
        const float* t = text;
        text = vision;
        vision = t;
    }
    cudaFuncSetAttribute(ShallowDecoder_kernel,
                         cudaFuncAttributeMaxDynamicSharedMemorySize, SMEM_BYTES);
    ShallowDecoder_kernel<<<256, 512, SMEM_BYTES>>>(text, vision, (float*)d_out);
}

// round 5
// speedup vs baseline: 1.0728x; 1.0195x over previous
#include <cuda_runtime.h>
#include <cuda_fp16.h>
#include <cstdint>

// ---------------- problem constants ----------------
constexpr int Dd   = 768;
constexpr int RS   = 256 * 768;            // row stride in floats (B*D)
constexpr int TEXT_ELEMS   = 77 * 256 * 768;
constexpr int VISION_ELEMS = 576 * 256 * 768;

// ---------------- smem layout (32-bit word offsets) ----------------
constexpr int S_STR = 580;                 // S row stride (fp32)
constexpr int STG   = 77 * S_STR + 12;     // 44672, 16B aligned
// phase-1 half2 tiles (1 word = 1 half2), k-pair stride 12 (8 pairs + pad 4)
constexpr int P1_TH = STG;                 // 96 x 12
constexpr int P1_TL = P1_TH + 96 * 12;
constexpr int P1_VH = P1_TL + 96 * 12;     // 192 x 12
constexpr int P1_VL = P1_VH + 192 * 12;
constexpr int P1_END = P1_VL + 192 * 12;   // 51584
// phase-2 half2 V tiles: [d=192][pair stride 20]
constexpr int P2_VH = STG;                 // 192 x 20
constexpr int P2_VL = P2_VH + 192 * 20;
constexpr int P2_END = P2_VL + 192 * 20;   // 52352
constexpr int SMEM_WORDS = (P1_END > P2_END ? P1_END : P2_END);
constexpr int SMEM_BYTES = SMEM_WORDS * 4; // 209408 (< 227KB)

__device__ __forceinline__ float ex2f(float x) {
    float y; asm("ex2.approx.f32 %0, %1;" : "=f"(y) : "f"(x)); return y;
}

// split a float2 into hi (fp16x2) and lo (fp16x2 of residual), packed as u32
__device__ __forceinline__ void split2(float2 x, uint32_t& h, uint32_t& l) {
    __half hx = __float2half_rn(x.x), hy = __float2half_rn(x.y);
    __half lx = __float2half_rn(x.x - __half2float(hx));
    __half ly = __float2half_rn(x.y - __half2float(hy));
    h = (uint32_t)__half_as_ushort(hx) | ((uint32_t)__half_as_ushort(hy) << 16);
    l = (uint32_t)__half_as_ushort(lx) | ((uint32_t)__half_as_ushort(ly) << 16);
}

// fp16 m16n8k16, fp32 accumulate
__device__ __forceinline__ void mma16(float* c,
                                      uint32_t a0, uint32_t a1, uint32_t a2, uint32_t a3,
                                      uint32_t b0, uint32_t b1) {
    asm volatile(
        "mma.sync.aligned.m16n8k16.row.col.f32.f16.f16.f32 "
        "{%0,%1,%2,%3}, {%4,%5,%6,%7}, {%8,%9}, {%0,%1,%2,%3};\n"
        : "+f"(c[0]), "+f"(c[1]), "+f"(c[2]), "+f"(c[3])
        : "r"(a0), "r"(a1), "r"(a2), "r"(a3), "r"(b0), "r"(b1));
}

extern __shared__ float sm[];

__global__ __launch_bounds__(512, 1)
void ShallowDecoder_kernel(const float* __restrict__ text,
                           const float* __restrict__ vision,
                           float* __restrict__ out) {
    const int b = blockIdx.x;
    const float* tb = text + (size_t)b * Dd;
    const float* vb = vision + (size_t)b * Dd;
    float* ob = out + (size_t)b * Dd;

    uint32_t* smu = (uint32_t*)sm;

    const int tid  = threadIdx.x;
    const int w    = tid >> 5;
    const int lane = tid & 31;
    const int wm   = w >> 3;      // 0..1 : 48 M-rows each
    const int wn   = w & 7;       // 0..7
    const int g    = lane >> 2;   // groupID
    const int c    = lane & 3;    // threadID_in_group

    // ================= Phase 1: S = T V^T (3xFP16, m16n8k16), N-tile 192 =================
    for (int nt = 0; nt < 3; ++nt) {
        const int nb = nt * 192;

        float acc[3][3][4];
        #pragma unroll
        for (int mt = 0; mt < 3; ++mt)
            #pragma unroll
            for (int nc = 0; nc < 3; ++nc)
                #pragma unroll
                for (int q = 0; q < 4; ++q) acc[mt][nc][q] = 0.f;

        float2 pT[2], pV[3];
        // prefetch chunk 0 (chunk = 16 floats = 8 k-pairs)
        #pragma unroll
        for (int q = 0; q < 2; ++q) {
            int i = tid + 512 * q;
            if (i < 616) {
                int m = i >> 3, j = i & 7;
                pT[q] = *(const float2*)(tb + (size_t)m * RS + 2 * j);
            }
        }
        #pragma unroll
        for (int q = 0; q < 3; ++q) {
            int i = tid + 512 * q;        // 0..1535
            int m = i >> 3, j = i & 7;    // m 0..191
            pV[q] = *(const float2*)(vb + (size_t)(nb + m) * RS + 2 * j);
        }

        for (int dc = 0; dc < 48; ++dc) {
            // stage prefetched regs -> smem hi/lo half2 tiles
            #pragma unroll
            for (int q = 0; q < 2; ++q) {
                int i = tid + 512 * q;
                if (i < 616) {
                    int m = i >> 3, j = i & 7;
                    uint32_t h, l;
                    split2(pT[q], h, l);
                    smu[P1_TH + m * 12 + j] = h;
                    smu[P1_TL + m * 12 + j] = l;
                }
            }
            #pragma unroll
            for (int q = 0; q < 3; ++q) {
                int i = tid + 512 * q;
                int m = i >> 3, j = i & 7;
                uint32_t h, l;
                split2(pV[q], h, l);
                smu[P1_VH + m * 12 + j] = h;
                smu[P1_VL + m * 12 + j] = l;
            }
            __syncthreads();

            // prefetch next chunk while mma runs
            if (dc < 47) {
                const int d0 = (dc + 1) * 16;
                #pragma unroll
                for (int q = 0; q < 2; ++q) {
                    int i = tid + 512 * q;
                    if (i < 616) {
                        int m = i >> 3, j = i & 7;
                        pT[q] = *(const float2*)(tb + (size_t)m * RS + d0 + 2 * j);
                    }
                }
                #pragma unroll
                for (int q = 0; q < 3; ++q) {
                    int i = tid + 512 * q;
                    int m = i >> 3, j = i & 7;
                    pV[q] = *(const float2*)(vb + (size_t)(nb + m) * RS + d0 + 2 * j);
                }
            }

            // one k16 step per chunk
            uint32_t bh0[3], bh1[3], bl0[3], bl1[3];
            #pragma unroll
            for (int nc = 0; nc < 3; ++nc) {
                int row = wn * 24 + nc * 8 + g;
                int ba  = row * 12 + c;
                bh0[nc] = smu[P1_VH + ba];     bh1[nc] = smu[P1_VH + ba + 4];
                bl0[nc] = smu[P1_VL + ba];     bl1[nc] = smu[P1_VL + ba + 4];
            }
            #pragma unroll
            for (int mt = 0; mt < 3; ++mt) {
                int r  = wm * 48 + mt * 16 + g;
                int aa = r * 12 + c;
                uint32_t ah0 = smu[P1_TH + aa];
                uint32_t ah1 = smu[P1_TH + aa + 8 * 12];
                uint32_t ah2 = smu[P1_TH + aa + 4];
                uint32_t ah3 = smu[P1_TH + aa + 8 * 12 + 4];
                uint32_t al0 = smu[P1_TL + aa];
                uint32_t al1 = smu[P1_TL + aa + 8 * 12];
                uint32_t al2 = smu[P1_TL + aa + 4];
                uint32_t al3 = smu[P1_TL + aa + 8 * 12 + 4];
                #pragma unroll
                for (int nc = 0; nc < 3; ++nc) {
                    mma16(acc[mt][nc], ah0, ah1, ah2, ah3, bh0[nc], bh1[nc]);
                    mma16(acc[mt][nc], ah0, ah1, ah2, ah3, bl0[nc], bl1[nc]);
                    mma16(acc[mt][nc], al0, al1, al2, al3, bh0[nc], bh1[nc]);
                }
            }
            __syncthreads();
        }

        // store S tile (guard rows < 77)
        #pragma unroll
        for (int mt = 0; mt < 3; ++mt) {
            int r0 = wm * 48 + mt * 16 + g, r1 = r0 + 8;
            #pragma unroll
            for (int nc = 0; nc < 3; ++nc) {
                int col = nb + wn * 24 + nc * 8 + 2 * c;
                if (r0 < 77)
                    *(float2*)&sm[r0 * S_STR + col] =
                        make_float2(acc[mt][nc][0], acc[mt][nc][1]);
                if (r1 < 77)
                    *(float2*)&sm[r1 * S_STR + col] =
                        make_float2(acc[mt][nc][2], acc[mt][nc][3]);
            }
        }
    }
    __syncthreads();

    // ================= Softmax over n (576), temp 0.07 =================
    {
        const float SCL = 20.60992915555662f; // log2(e)/0.07
        for (int r = w; r < 77; r += 16) {
            float v[18];
            float mx = -1e30f;
            #pragma unroll
            for (int j = 0; j < 18; ++j) {
                v[j] = sm[r * S_STR + lane + 32 * j];
                mx = fmaxf(mx, v[j]);
            }
            #pragma unroll
            for (int o = 16; o > 0; o >>= 1)
                mx = fmaxf(mx, __shfl_xor_sync(0xffffffffu, mx, o));
            float sum = 0.f;
            #pragma unroll
            for (int j = 0; j < 18; ++j) {
                v[j] = ex2f((v[j] - mx) * SCL);
                sum += v[j];
            }
            #pragma unroll
            for (int o = 16; o > 0; o >>= 1)
                sum += __shfl_xor_sync(0xffffffffu, sum, o);
            float rinv = 1.0f / sum;
            #pragma unroll
            for (int j = 0; j < 18; ++j)
                sm[r * S_STR + lane + 32 * j] = v[j] * rinv;
        }
    }
    __syncthreads();

    // ================= Phase 2: O = A V (3xFP16, m16n8k16), d-tile 192 =================
    int arow[3][2];
    #pragma unroll
    for (int mt = 0; mt < 3; ++mt) {
        int r0 = wm * 48 + mt * 16 + g;
        int r1 = r0 + 8;
        arow[mt][0] = (r0 > 76 ? 76 : r0) * S_STR;
        arow[mt][1] = (r1 > 76 ? 76 : r1) * S_STR;
    }

    for (int dt = 0; dt < 4; ++dt) {
        const int db = dt * 192;

        float acc[3][3][4];
        #pragma unroll
        for (int mt = 0; mt < 3; ++mt)
            #pragma unroll
            for (int d8 = 0; d8 < 3; ++d8)
                #pragma unroll
                for (int q = 0; q < 4; ++q) acc[mt][d8][q] = 0.f;

        // V staging: warp w <-> n-pair p (16 pairs per 32-n chunk); lanes -> d
        float pv0[6], pv1[6];
        #pragma unroll
        for (int it = 0; it < 6; ++it) {
            int d = lane + 32 * it;
            pv0[it] = vb[(size_t)(2 * w) * RS + db + d];
            pv1[it] = vb[(size_t)(2 * w + 1) * RS + db + d];
        }

        for (int ch = 0; ch < 18; ++ch) {
            #pragma unroll
            for (int it = 0; it < 6; ++it) {
                int d = lane + 32 * it;
                uint32_t h, l;
                split2(make_float2(pv0[it], pv1[it]), h, l);
                smu[P2_VH + d * 20 + w] = h;
                smu[P2_VL + d * 20 + w] = l;
            }
            __syncthreads();

            if (ch < 17) {
                const int n0 = (ch + 1) * 32 + 2 * w;
                #pragma unroll
                for (int it = 0; it < 6; ++it) {
                    int d = lane + 32 * it;
                    pv0[it] = vb[(size_t)n0 * RS + db + d];
                    pv1[it] = vb[(size_t)(n0 + 1) * RS + db + d];
                }
            }

            const int nbase = ch * 32;
            #pragma unroll
            for (int kk = 0; kk < 2; ++kk) {
                uint32_t bh0[3], bh1[3], bl0[3], bl1[3];
                #pragma unroll
                for (int d8 = 0; d8 < 3; ++d8) {
                    int col = wn * 24 + d8 * 8 + g;
                    int bp  = kk * 8 + c;
                    bh0[d8] = smu[P2_VH + col * 20 + bp];
                    bh1[d8] = smu[P2_VH + col * 20 + bp + 4];
                    bl0[d8] = smu[P2_VL + col * 20 + bp];
                    bl1[d8] = smu[P2_VL + col * 20 + bp + 4];
                }
                #pragma unroll
                for (int mt = 0; mt < 3; ++mt) {
                    int ca = nbase + kk * 16 + 2 * c;
                    float2 f0 = *(float2*)&sm[arow[mt][0] + ca];
                    float2 f1 = *(float2*)&sm[arow[mt][1] + ca];
                    float2 f2 = *(float2*)&sm[arow[mt][0] + ca + 8];
                    float2 f3 = *(float2*)&sm[arow[mt][1] + ca + 8];
                    uint32_t ah0, al0, ah1, al1, ah2, al2, ah3, al3;
                    split2(f0, ah0, al0);
                    split2(f1, ah1, al1);
                    split2(f2, ah2, al2);
                    split2(f3, ah3, al3);
                    #pragma unroll
                    for (int d8 = 0; d8 < 3; ++d8) {
                        mma16(acc[mt][d8], ah0, ah1, ah2, ah3, bh0[d8], bh1[d8]);
                        mma16(acc[mt][d8], ah0, ah1, ah2, ah3, bl0[d8], bl1[d8]);
                        mma16(acc[mt][d8], al0, al1, al2, al3, bh0[d8], bh1[d8]);
                    }
                }
            }
            __syncthreads();
        }

        // store output tile (fp32, guard rows < 77)
        #pragma unroll
        for (int mt = 0; mt < 3; ++mt) {
            int r0 = wm * 48 + mt * 16 + g, r1 = r0 + 8;
            #pragma unroll
            for (int d8 = 0; d8 < 3; ++d8) {
                int col = db + wn * 24 + d8 * 8 + 2 * c;
                if (r0 < 77)
                    *(float2*)(ob + (size_t)r0 * RS + col) =
                        make_float2(acc[mt][d8][0], acc[mt][d8][1]);
                if (r1 < 77)
                    *(float2*)(ob + (size_t)r1 * RS + col) =
                        make_float2(acc[mt][d8][2], acc[mt][d8][3]);
            }
        }
    }
}

extern "C" void kernel_launch(void* const* d_in, const int* in_sizes, int n_in,
                              void* d_out, int out_size) {
    const float* text   = (const float*)d_in[0];
    const float* vision = (const float*)d_in[1];
    if (n_in >= 2 && in_sizes[0] == VISION_ELEMS && in_sizes[1] == TEXT_ELEMS) {
        const float* t = text; text = vision; vision = t;
    }
    cudaFuncSetAttribute(ShallowDecoder_kernel,
                         cudaFuncAttributeMaxDynamicSharedMemorySize, SMEM_BYTES);
    ShallowDecoder_kernel<<<256, 512, SMEM_BYTES>>>(text, vision, (float*)d_out);
}